// round 10
// baseline (speedup 1.0000x reference)
#include <cuda_runtime.h>
#include <cuda_bf16.h>

#define B_   8
#define N_   1024
#define IN_  512
#define H_   8
#define SUP_ 64
#define BH_  (B_*H_)      // 64
#define ROWS_ (B_*N_)     // 8192

// Scratch (no cudaMalloc allowed). float4-typed for guaranteed 16B alignment.
__device__ float4 g_inputsv[BH_ * N_ * SUP_ / 4];   // [bh][n][o] 16.8 MB
__device__ float4 g_s4[BH_ * N_];                   // {s, e^s, e^{0.01s}, 0}
__device__ float4 g_t4[BH_ * N_];                   // {t, e^t, e^{0.01t}, 0}

// ---------- helpers ----------
__device__ __forceinline__ unsigned long long pack2(float x, float y){
    unsigned long long r;
    asm("mov.b64 %0, {%1, %2};" : "=l"(r) : "f"(x), "f"(y));
    return r;
}
__device__ __forceinline__ void fma2(unsigned long long &d, unsigned long long a, unsigned long long b){
    asm("fma.rn.f32x2 %0, %1, %2, %0;" : "+l"(d) : "l"(a), "l"(b));
}
__device__ __forceinline__ float2 unpack2(unsigned long long v){
    float2 f;
    asm("mov.b64 {%0, %1}, %2;" : "=f"(f.x), "=f"(f.y) : "l"(v));
    return f;
}
__device__ __forceinline__ unsigned smem_u32(const void* p){
    unsigned a;
    asm("{ .reg .u64 t; cvta.to.shared.u64 t, %1; cvt.u32.u64 %0, t; }" : "=r"(a) : "l"(p));
    return a;
}
__device__ __forceinline__ void cpa16(unsigned dst, const void* src){
    asm volatile("cp.async.cg.shared.global [%0], [%1], 16;" :: "r"(dst), "l"(src));
}
__device__ __forceinline__ void cpa_commit(){ asm volatile("cp.async.commit_group;"); }
__device__ __forceinline__ void cpa_wait0(){ asm volatile("cp.async.wait_group 0;"); }

// ---------- polynomial exp (262K calls, fc kernel only) ----------
__device__ __forceinline__ float fast_exp(float x){
    float t = x * 1.4426950408889634f;
    t = fmaxf(t, -80.0f);
    float r = t + 12582912.0f;
    float f = t - (r - 12582912.0f);
    int   n = __float_as_int(r) - 0x4B400000;
    float p = 1.33335581e-3f;
    p = fmaf(p, f, 9.61812911e-3f);
    p = fmaf(p, f, 5.55041087e-2f);
    p = fmaf(p, f, 2.40226507e-1f);
    p = fmaf(p, f, 6.93147181e-1f);
    p = fmaf(p, f, 1.0f);
    return __int_as_float(__float_as_int(p) + (n << 23));
}

// 64-col half-shift swizzle -> conflict-free 8-chunk LDS.128 phases (stride 72)
#define WOFF(c) ((c) + (((c) >> 5) << 2))

#define PXS_TILE (256 * 32)        // X buffer floats (stride 32, XOR-chunk swizzled)
#define PWS_TILE (32 * 72)         // W buffer floats
#define PROJ_SMEM ((2 * PXS_TILE + 2 * PWS_TILE) * 4)   // 83968 B

// ============================================================
// Kernel A: per-head projection  inputs[bh][n][o] = X[b,n,:] @ W[h,:,o]
// CTA: 256 rows x 64 cols (one head), 256 threads, 8 rows x 8 cols/thread,
// cols-in-u64 acc (32 u64). Xs: stride 32, chunk c stored at c ^ (row>>3 & 7)
// so the 4 distinct warp rows (congruent mod 8) land on distinct banks.
// ============================================================
__global__ __launch_bounds__(256, 2) void proj_kernel(const float* __restrict__ X,
                                                      const float* __restrict__ W){
    extern __shared__ __align__(16) float sm[];
    float* Xs = sm;                        // [2][256][32]
    float* Ws = sm + 2 * PXS_TILE;         // [2][32][72]

    const int h   = blockIdx.y;
    const int R0  = blockIdx.x * 256;
    const int tid = threadIdx.x;
    const int colg = tid & 7, rowg = tid >> 3;       // 8 colg x 32 rowg
    const int c0   = colg * 8;
    const int rbase = rowg * 8;
    const int wo   = WOFF(c0);
    const int sx   = (rowg & 7) << 2;                // per-thread XOR for Xs k index

    const float* Wh = W + (size_t)h * (IN_ * SUP_);

    const unsigned xs_base = smem_u32(Xs);
    const unsigned ws_base = smem_u32(Ws);

    auto stage = [&](int kt, int p){
        // X: 256 rows x 32 k = 2048 float4, 8 per thread, chunk-XOR swizzled dst
#pragma unroll
        for (int j = 0; j < 8; j++){
            int fid = tid + j * 256;
            int row = fid >> 3, c = fid & 7;
            int dc  = c ^ ((row >> 3) & 7);
            cpa16(xs_base + (unsigned)(p * PXS_TILE + row * 32 + dc * 4) * 4u,
                  X + (size_t)(R0 + row) * IN_ + kt + c * 4);
        }
        // W: 32 k x 64 cols = 512 float4, 2 per thread, WOFF swizzled dst
#pragma unroll
        for (int j = 0; j < 2; j++){
            int fid = tid + j * 256;
            int kk = fid >> 4, cc = (fid & 15) * 4;
            cpa16(ws_base + (unsigned)(p * PWS_TILE + kk * 72 + WOFF(cc)) * 4u,
                  Wh + (size_t)(kt + kk) * SUP_ + cc);
        }
        cpa_commit();
    };

    unsigned long long acc[8][4];          // [row i][col-pair]
#pragma unroll
    for (int i = 0; i < 8; i++)
#pragma unroll
        for (int c = 0; c < 4; c++) acc[i][c] = 0ull;

    stage(0, 0);

    for (int t = 0; t < IN_ / 32; t++){
        const int p = t & 1;
        cpa_wait0();
        __syncthreads();
        if (t + 1 < IN_ / 32) stage((t + 1) * 32, p ^ 1);

        const float* Xp = Xs + p * PXS_TILE + rbase * 32;
        const float* Wp = Ws + p * PWS_TILE;
#pragma unroll 8
        for (int k = 0; k < 32; k++){
            const float* wk = &Wp[k * 72 + wo];
            ulonglong2 w0 = *(const ulonglong2*)(wk);       // col pairs 0,1
            ulonglong2 w1 = *(const ulonglong2*)(wk + 4);   // col pairs 2,3
            const int kx = k ^ sx;
#pragma unroll
            for (int i = 0; i < 8; i++){
                float a = Xp[i * 32 + kx];
                unsigned long long aa = pack2(a, a);
                fma2(acc[i][0], w0.x, aa);
                fma2(acc[i][1], w0.y, aa);
                fma2(acc[i][2], w1.x, aa);
                fma2(acc[i][3], w1.y, aa);
            }
        }
    }

    float* gi = (float*)g_inputsv;
#pragma unroll
    for (int i = 0; i < 8; i++){
        int R = R0 + rbase + i;
        int b = R >> 10, n = R & 1023;
        float2 v0 = unpack2(acc[i][0]);
        float2 v1 = unpack2(acc[i][1]);
        float2 v2 = unpack2(acc[i][2]);
        float2 v3 = unpack2(acc[i][3]);
        float* dst = gi + ((size_t)(b * H_ + h) * N_ + n) * SUP_ + c0;
        *(float4*)dst       = make_float4(v0.x, v0.y, v1.x, v1.y);
        *(float4*)(dst + 4) = make_float4(v2.x, v2.y, v3.x, v3.y);
    }
}

// ============================================================
// Kernel B: s/t logit pieces + factored exponentials
// ============================================================
__global__ __launch_bounds__(256) void fc_kernel(const float* __restrict__ w1, const float* __restrict__ b1,
                                                 const float* __restrict__ w2, const float* __restrict__ b2){
    int rid  = blockIdx.x * 8 + (threadIdx.x >> 5);   // 0..65535
    int lane = threadIdx.x & 31;
    int h    = (rid >> 10) & 7;
    const float* row = (const float*)g_inputsv + (size_t)rid * 64;
    float v0 = row[lane], v1 = row[lane + 32];
    float d1 = v0 * w1[h * 64 + lane] + v1 * w1[h * 64 + 32 + lane];
    float d2 = v0 * w2[h * 64 + lane] + v1 * w2[h * 64 + 32 + lane];
#pragma unroll
    for (int off = 16; off >= 1; off >>= 1){
        d1 += __shfl_xor_sync(0xffffffffu, d1, off);
        d2 += __shfl_xor_sync(0xffffffffu, d2, off);
    }
    if (lane == 0){
        float s = d1 + b1[h];
        float t = d2 + b2[h];
        g_s4[rid] = make_float4(s, fast_exp(s), fast_exp(0.01f * s), 0.f);
        g_t4[rid] = make_float4(t, fast_exp(t), fast_exp(0.01f * t), 0.f);
    }
}

// ============================================================
// Kernel C: fused masked-softmax attention + aggregation + relu
// CTA = one (b,h) x 256 rows, 256 threads, 8 rows x 8 cols/thread.
// e_s[m][row] stride 258 -> LDS.64 row-pairs; in_s stride 72 + WOFF;
// acc[4 rowpair][8 col] = 32 u64; denom: one thread per row, no reduction.
// ============================================================
#define MT_ 32
#define IN_TILE (MT_ * 72)                 // 2304 floats per buffer
#define ESTR 258
#define ATTN_SMEM ((2*IN_TILE + MT_*ESTR + 4*256 + 4*2*MT_ + 256) * 4)

__global__ __launch_bounds__(256, 2) void attn_kernel(const float* __restrict__ A,
                                                      float* __restrict__ out){
    extern __shared__ __align__(16) float smA[];
    float*  in_s    = smA;                              // [2][32][72]
    float*  e_s     = smA + 2 * IN_TILE;                // [32][258]
    float4* s4_s    = (float4*)(smA + 2 * IN_TILE + MT_ * ESTR);   // [256]
    float4* t4_s    = s4_s + 256;                       // [2][32]
    float*  denom_s = (float*)(t4_s + 2 * MT_);         // [256]

    const int bh  = blockIdx.y;
    const int b   = bh >> 3, h = bh & 7;
    const int R0  = blockIdx.x * 256;
    const int tid = threadIdx.x;
    const int colg = tid & 7, rowg = tid >> 3;
    const int c0   = colg * 8;
    const int rb   = rowg * 8;
    const int wo   = WOFF(c0);

    // e-phase identity: row = erow0 + 32j (j<8), 4 m per row via float4 A
    const int erow0 = tid >> 3;
    const int em0   = (tid & 7) * 4;

    s4_s[tid] = g_s4[(size_t)bh * N_ + R0 + tid];

    const float*  Ab     = A + ((size_t)b * N_ + R0) * N_;
    const float*  inbase = (const float*)g_inputsv + (size_t)bh * (N_ * SUP_);
    const float4* t4g    = g_t4 + (size_t)bh * N_;

    const unsigned in_u = smem_u32(in_s);
    const unsigned t4_u = smem_u32(t4_s);

    auto stage = [&](int mt, int p){
        // inputs m-tile: 512 float4, 2 per thread, WOFF swizzled (stride 72)
#pragma unroll
        for (int j = 0; j < 2; j++){
            int fid = tid + j * 256;
            int m = fid >> 4, c = (fid & 15) * 4;
            cpa16(in_u + (unsigned)(p * IN_TILE + m * 72 + WOFF(c)) * 4u,
                  (const float*)(inbase + (size_t)(mt + m) * SUP_ + c));
        }
        if (tid < MT_) cpa16(t4_u + (unsigned)(p * MT_ + tid) * 16u, t4g + mt + tid);
        cpa_commit();
    };

    unsigned long long acc[4][8];          // [row-pair][col]
#pragma unroll
    for (int i = 0; i < 4; i++)
#pragma unroll
        for (int c = 0; c < 8; c++) acc[i][c] = 0ull;
    float dreg = 0.f;

    stage(0, 0);

    for (int t = 0; t < N_ / MT_; t++){
        const int p  = t & 1;
        const int mt = t * MT_;
        cpa_wait0();
        __syncthreads();
        if (t + 1 < N_ / MT_) stage(mt + MT_, p ^ 1);

        const float4* t4p = t4_s + p * MT_;
        // e-phase: 256 rows x 32 m
#pragma unroll
        for (int j = 0; j < 8; j++){
            int row = erow0 + j * 32;
            float4 sr = s4_s[row];
            float4 a4 = *(const float4*)(Ab + (size_t)row * N_ + mt + em0);
            float4 t0 = t4p[em0 + 0];
            float4 t1 = t4p[em0 + 1];
            float4 t2 = t4p[em0 + 2];
            float4 t3 = t4p[em0 + 3];
            float thr = -sr.x;
            e_s[(em0 + 0) * ESTR + row] = a4.x * ((t0.x >= thr) ? (sr.y * t0.y) : (sr.z * t0.z));
            e_s[(em0 + 1) * ESTR + row] = a4.y * ((t1.x >= thr) ? (sr.y * t1.y) : (sr.z * t1.z));
            e_s[(em0 + 2) * ESTR + row] = a4.z * ((t2.x >= thr) ? (sr.y * t2.y) : (sr.z * t2.z));
            e_s[(em0 + 3) * ESTR + row] = a4.w * ((t3.x >= thr) ? (sr.y * t3.y) : (sr.z * t3.z));
        }
        __syncthreads();

        // denominator: one thread per row, sums all 32 m
        {
            const float* ep = e_s + tid;
            float ds = 0.f;
#pragma unroll
            for (int m = 0; m < MT_; m++) ds += ep[m * ESTR];
            dreg += ds;
        }

        // fma phase
        const float* inp = in_s + p * IN_TILE;
#pragma unroll 4
        for (int m = 0; m < MT_; m++){
            const float* ep = e_s + m * ESTR + rb;
            unsigned long long e0 = *(const unsigned long long*)(ep);
            unsigned long long e1 = *(const unsigned long long*)(ep + 2);
            unsigned long long e2 = *(const unsigned long long*)(ep + 4);
            unsigned long long e3 = *(const unsigned long long*)(ep + 6);
            const float* xr = inp + m * 72 + wo;
            float4 xa = *(const float4*)(xr);
            float4 xb = *(const float4*)(xr + 4);
            unsigned long long xd[8];
            xd[0] = pack2(xa.x, xa.x); xd[1] = pack2(xa.y, xa.y);
            xd[2] = pack2(xa.z, xa.z); xd[3] = pack2(xa.w, xa.w);
            xd[4] = pack2(xb.x, xb.x); xd[5] = pack2(xb.y, xb.y);
            xd[6] = pack2(xb.z, xb.z); xd[7] = pack2(xb.w, xb.w);
#pragma unroll
            for (int c = 0; c < 8; c++){
                fma2(acc[0][c], e0, xd[c]);
                fma2(acc[1][c], e1, xd[c]);
                fma2(acc[2][c], e2, xd[c]);
                fma2(acc[3][c], e3, xd[c]);
            }
        }
    }

    denom_s[tid] = dreg;
    __syncthreads();

#pragma unroll
    for (int pI = 0; pI < 4; pI++){
        int r0 = rb + 2 * pI;                         // local rows r0, r0+1
        float inv0 = 1.0f / denom_s[r0];
        float inv1 = 1.0f / denom_s[r0 + 1];
        float lo[8], hi[8];
#pragma unroll
        for (int c = 0; c < 8; c++){
            float2 v = unpack2(acc[pI][c]);
            lo[c] = v.x; hi[c] = v.y;
        }
        float* op0 = out + ((size_t)(b * N_ + R0 + r0)) * (H_ * SUP_) + h * SUP_ + c0;
        float* op1 = op0 + (H_ * SUP_);
        *(float4*)op0       = make_float4(fmaxf(lo[0],0.f)*inv0, fmaxf(lo[1],0.f)*inv0,
                                          fmaxf(lo[2],0.f)*inv0, fmaxf(lo[3],0.f)*inv0);
        *(float4*)(op0 + 4) = make_float4(fmaxf(lo[4],0.f)*inv0, fmaxf(lo[5],0.f)*inv0,
                                          fmaxf(lo[6],0.f)*inv0, fmaxf(lo[7],0.f)*inv0);
        *(float4*)op1       = make_float4(fmaxf(hi[0],0.f)*inv1, fmaxf(hi[1],0.f)*inv1,
                                          fmaxf(hi[2],0.f)*inv1, fmaxf(hi[3],0.f)*inv1);
        *(float4*)(op1 + 4) = make_float4(fmaxf(hi[4],0.f)*inv1, fmaxf(hi[5],0.f)*inv1,
                                          fmaxf(hi[6],0.f)*inv1, fmaxf(hi[7],0.f)*inv1);
    }
}

// ============================================================
extern "C" void kernel_launch(void* const* d_in, const int* in_sizes, int n_in,
                              void* d_out, int out_size){
    // match inputs by element count: A=8388608, X=4194304, W=262144, w1/w2=512, b1/b2=8
    const float *A = nullptr, *X = nullptr, *W = nullptr;
    const float *w1 = nullptr, *w2 = nullptr, *b1 = nullptr, *b2 = nullptr;
    for (int i = 0; i < n_in; i++){
        const float* p = (const float*)d_in[i];
        switch (in_sizes[i]){
            case 8388608: A = p; break;
            case 4194304: X = p; break;
            case 262144:  W = p; break;
            case 512:     (w1 ? w2 : w1) = p; break;
            case 8:       (b1 ? b2 : b1) = p; break;
            default: break;
        }
    }
    float* out = (float*)d_out;

    cudaFuncSetAttribute(proj_kernel, cudaFuncAttributeMaxDynamicSharedMemorySize, PROJ_SMEM);
    cudaFuncSetAttribute(attn_kernel, cudaFuncAttributeMaxDynamicSharedMemorySize, ATTN_SMEM);

    proj_kernel<<<dim3(ROWS_ / 256, H_), 256, PROJ_SMEM>>>(X, W);
    fc_kernel<<<BH_ * N_ / 8, 256>>>(w1, b1, w2, b2);
    attn_kernel<<<dim3(N_ / 256, BH_), 256, ATTN_SMEM>>>(A, out);
}